// round 7
// baseline (speedup 1.0000x reference)
#include <cuda_runtime.h>

// Flow-warp bilinear, direct gather, 2 x-adjacent pixels per thread:
// float2 flow loads, float2 output stores, full 16-channel unroll.
// out[b,c,y,x] = bilerp(src[b,c], clamp(y+flow[b,0,y,x]), clamp(x+flow[b,1,y,x]))
// B=8, C=16, H=W=512.
// Edge trick: clamp x0,y0 to <=510; when floor hits 511 the fractional weight
// becomes exactly 1.0 so the result is identical and +1 taps stay in bounds.

#define B_ 8
#define C_ 16
#define H_ 512
#define W_ 512
#define HW_ (H_ * W_)
#define CHW_ (C_ * HW_)

__global__ void __launch_bounds__(256) warp_gatherx2_kernel(
    const float* __restrict__ src,
    const float* __restrict__ flow,
    float* __restrict__ out)
{
    int idx = blockIdx.x * blockDim.x + threadIdx.x;   // over B * H * W/2
    int xh  = idx & 255;            // x-pair index
    int y   = (idx >> 8) & 511;
    int b   = idx >> 17;
    int x   = xh << 1;              // even x

    const float* __restrict__ fby = flow + b * 2 * HW_;
    const float* __restrict__ fbx = fby + HW_;
    int fo = y * W_ + x;

    float2 fy2 = *(const float2*)(fby + fo);   // dy for pixels x, x+1
    float2 fx2 = *(const float2*)(fbx + fo);   // dx for pixels x, x+1

    int   g00[2];
    float wxv[2], wyv[2];

#pragma unroll
    for (int k = 0; k < 2; ++k) {
        float fy = k ? fy2.y : fy2.x;
        float fx = k ? fx2.y : fx2.x;
        // reference's normalize->unnormalize cancels exactly
        float py = fminf(fmaxf((float)y + fy, 0.0f), (float)(H_ - 1));
        float px = fminf(fmaxf((float)(x + k) + fx, 0.0f), (float)(W_ - 1));
        float y0f = floorf(py);
        float x0f = floorf(px);
        int y0 = min((int)y0f, H_ - 2);
        int x0 = min((int)x0f, W_ - 2);
        wyv[k] = py - (float)y0;
        wxv[k] = px - (float)x0;
        g00[k] = (y0 << 9) + x0;
    }

    const float* __restrict__ sb = src + b * CHW_;
    float* __restrict__ ob = out + b * CHW_ + fo;

    const int gA = g00[0];
    const int gB = g00[1];

#pragma unroll
    for (int c = 0; c < C_; ++c) {
        const float* __restrict__ sc = sb + c * HW_;
        float a00 = __ldg(sc + gA);
        float a01 = __ldg(sc + gA + 1);
        float a10 = __ldg(sc + gA + W_);
        float a11 = __ldg(sc + gA + W_ + 1);
        float b00 = __ldg(sc + gB);
        float b01 = __ldg(sc + gB + 1);
        float b10 = __ldg(sc + gB + W_);
        float b11 = __ldg(sc + gB + W_ + 1);

        float atop = fmaf(wxv[0], a01 - a00, a00);
        float abot = fmaf(wxv[0], a11 - a10, a10);
        float btop = fmaf(wxv[1], b01 - b00, b00);
        float bbot = fmaf(wxv[1], b11 - b10, b10);

        float2 res;
        res.x = fmaf(wyv[0], abot - atop, atop);
        res.y = fmaf(wyv[1], bbot - btop, btop);
        *(float2*)(ob + c * HW_) = res;
    }
}

extern "C" void kernel_launch(void* const* d_in, const int* in_sizes, int n_in,
                              void* d_out, int out_size)
{
    const float* src  = (const float*)d_in[0];
    const float* flow = (const float*)d_in[1];
    float* out        = (float*)d_out;

    const int total = B_ * H_ * (W_ / 2);   // 1,048,576 threads
    warp_gatherx2_kernel<<<total / 256, 256>>>(src, flow, out);
}